// round 11
// baseline (speedup 1.0000x reference)
#include <cuda_runtime.h>

#define N_CELLS 776
#define N_ANCHORS 3
#define N_CH 7
#define CONF_THRESH 0.8f
#define NO_OBJECT 0.5f

#define CELL_F      (N_ANCHORS * N_CH)          // 21 floats/cell
#define TOTAL_F     (N_CELLS * CELL_F)          // 16296 floats
#define TOTAL_V4    (TOTAL_F / 4)               // 4074 float4
#define CELLS_PER_CTA 32
#define N_CTAS      ((N_CELLS + CELLS_PER_CTA - 1) / CELLS_PER_CTA)  // 25
#define CTA_F       (CELLS_PER_CTA * CELL_F)    // 672 floats
#define CTA_V4      (CTA_F / 4)                 // 168 float4

// Packed accumulator: bits [0,56) = fixed-point sum (scale 2^40, all partials
// >= 0), bits [56,64) = arrival count. Zero-init at load; last CTA resets it
// each replay. Integer adds are commutative -> bitwise-deterministic result.
#define COUNT_ONE   (1ULL << 56)
#define SUM_MASK    (COUNT_ONE - 1ULL)
__device__ unsigned long long g_accum;

__device__ __forceinline__ float sqrt_approx(float x) {
    float y;
    asm("sqrt.approx.f32 %0, %1;" : "=f"(y) : "f"(x));
    return y;
}

__global__ __launch_bounds__(32, 1)
void yolo_loss_kernel(const float* __restrict__ pred,
                      const float* __restrict__ label,
                      float* __restrict__ out) {
    __shared__ float sh[CTA_F];   // 2688 B: this CTA's 32 cells

    const int lane = threadIdx.x;
    const int bid  = blockIdx.x;

    // ---- stage this CTA's cells into smem (coalesced float4) ----
    {
        const float4* __restrict__ pv = (const float4*)pred;
        float4* sv = (float4*)sh;
        const int base = bid * CTA_V4;
        #pragma unroll
        for (int i = 0; i < 6; i++) {                 // 6*32 = 192 >= 168
            const int li = lane + i * 32;
            if (li < CTA_V4 && base + li < TOTAL_V4)
                sv[li] = pv[base + li];
        }
    }

    const float lx = __ldg(&label[0]);
    const float ly = __ldg(&label[1]);
    const float lw = __ldg(&label[2]);
    const float lh = __ldg(&label[3]);
    const float lc = __ldg(&label[4]);
    const float l5 = __ldg(&label[5]);
    const float l6 = __ldg(&label[6]);
    const float area_b = fabsf(lw * lh);
    const float sqlx = sqrt_approx(lx);
    const float sqly = sqrt_approx(ly);

    __syncwarp();

    // ---- per-cell loss ----
    float local = 0.0f;
    const int cell = bid * CELLS_PER_CTA + lane;
    if (cell < N_CELLS) {
        const float* c = sh + lane * CELL_F;   // stride 21 words: conflict-free

        float v[CELL_F];
        #pragma unroll
        for (int i = 0; i < CELL_F; i++) v[i] = c[i];

        float inter[N_ANCHORS], den[N_ANCHORS];
        #pragma unroll
        for (int a = 0; a < N_ANCHORS; a++) {
            const float px = v[a * N_CH + 0];
            const float py = v[a * N_CH + 1];
            const float pw = v[a * N_CH + 2];
            const float ph = v[a * N_CH + 3];
            const float ax = fmaxf(px - pw * 0.5f, lx - lw * 0.5f);
            const float ay = fmaxf(py - ph * 0.5f, ly - lh * 0.5f);
            const float bx = fminf(px + pw * 0.5f, lx + lw * 0.5f);
            const float by = fminf(py + ph * 0.5f, ly + lh * 0.5f);
            const float in = fabsf(fmaxf(bx - ax, 0.0f) * fmaxf(by - ay, 0.0f));
            inter[a] = in;
            den[a] = fabsf(pw * ph) + area_b - in;   // union area > 0
        }

        // Division-free argmax, strict > keeps first max (jnp.argmax).
        int best = 0;
        if (inter[1] * den[0] > inter[0] * den[1]) best = 1;
        if (inter[2] * den[best] > inter[best] * den[2]) best = 2;

        const float b0 = v[best * N_CH + 0];
        const float b1 = v[best * N_CH + 1];
        const float b4 = v[best * N_CH + 4];
        const float b5 = v[best * N_CH + 5];
        const float b6 = v[best * N_CH + 6];

        const float dx = lx - b0;
        const float dy = ly - b1;
        const float xy_loss = dx * dx + dy * dy;

        // Reference uses label[0]/label[1], best[:,0]/best[:,1] in the sqrt
        // terms — replicated verbatim.
        const float swx = sqlx - sqrt_approx(b0);
        const float swy = sqly - sqrt_approx(b1);
        const float wh_loss = swx * swx + swy * swy;

        const bool has_obj = b4 > CONF_THRESH;
        float class_loss = 0.0f;
        if (has_obj) {
            const float d5 = l5 - b5;
            const float d6 = l6 - b6;
            class_loss = d5 * d5 + d6 * d6;
        }
        const float dc = lc - b4;
        const float conf_sq = dc * dc;
        const float conf_loss = has_obj ? conf_sq : NO_OBJECT * conf_sq;

        local = xy_loss + wh_loss + class_loss + conf_loss;
    }

    // ---- warp reduce (fixed order -> deterministic) ----
    #pragma unroll
    for (int off = 16; off > 0; off >>= 1)
        local += __shfl_down_sync(0xFFFFFFFFu, local, off);

    // ---- cross-CTA: single packed atomicAdd; last arrival finishes ----
    if (lane == 0) {
        // local >= 0 always (sum of squares / scaled squares).
        const unsigned long long fixed =
            (unsigned long long)__double2ll_rn((double)local * 0x1p40);
        const unsigned long long packed = fixed + COUNT_ONE;
        const unsigned long long old = atomicAdd(&g_accum, packed);
        const unsigned long long now = old + packed;
        if ((now >> 56) == (unsigned long long)N_CTAS) {
            // Last CTA: full sum already in-register. Store & reset.
            const double total = (double)(long long)(now & SUM_MASK) * 0x1p-40;
            out[0] = (float)total;
            atomicExch(&g_accum, 0ULL);   // ready for next graph replay
        }
    }
}

extern "C" void kernel_launch(void* const* d_in, const int* in_sizes, int n_in,
                              void* d_out, int out_size) {
    const float* pred  = (const float*)d_in[0];
    const float* label = (const float*)d_in[1];
    float* out = (float*)d_out;
    yolo_loss_kernel<<<N_CTAS, 32>>>(pred, label, out);
}

// round 14
// speedup vs baseline: 1.0337x; 1.0337x over previous
#include <cuda_runtime.h>

#define N_CELLS 776
#define N_ANCHORS 3
#define N_CH 7
#define CONF_THRESH 0.8f
#define NO_OBJECT 0.5f

#define CELL_F      (N_ANCHORS * N_CH)          // 21 floats/cell
#define TOTAL_F     (N_CELLS * CELL_F)          // 16296 floats
#define TOTAL_V4    (TOTAL_F / 4)               // 4074 float4
#define THREADS_PER_CTA 128
#define CELLS_PER_CTA   THREADS_PER_CTA         // 1 cell per thread
#define N_CTAS      ((N_CELLS + CELLS_PER_CTA - 1) / CELLS_PER_CTA)  // 7
#define CTA_F       (CELLS_PER_CTA * CELL_F)    // 2688 floats
#define CTA_V4      (CTA_F / 4)                 // 672 float4

// Packed accumulator: bits [0,56) = fixed-point sum (scale 2^40, all partials
// >= 0), bits [56,64) = arrival count. Zero-init at load; last CTA resets it
// each replay. Integer adds are commutative -> bitwise-deterministic result.
#define COUNT_ONE   (1ULL << 56)
#define SUM_MASK    (COUNT_ONE - 1ULL)
__device__ unsigned long long g_accum;

__device__ __forceinline__ float sqrt_approx(float x) {
    float y;
    asm("sqrt.approx.f32 %0, %1;" : "=f"(y) : "f"(x));
    return y;
}

__global__ __launch_bounds__(THREADS_PER_CTA, 1)
void yolo_loss_kernel(const float* __restrict__ pred,
                      const float* __restrict__ label,
                      float* __restrict__ out) {
    __shared__ float sh[CTA_F];       // 10752 B: this CTA's 128 cells
    __shared__ float warp_sums[4];

    const int tid  = threadIdx.x;
    const int lane = tid & 31;
    const int wid  = tid >> 5;
    const int bid  = blockIdx.x;

    // Label loads first so they overlap the pred staging round trip.
    const float lx = __ldg(&label[0]);
    const float ly = __ldg(&label[1]);
    const float lw = __ldg(&label[2]);
    const float lh = __ldg(&label[3]);
    const float lc = __ldg(&label[4]);
    const float l5 = __ldg(&label[5]);
    const float l6 = __ldg(&label[6]);

    // ---- stage this CTA's cells into smem (coalesced float4) ----
    {
        const float4* __restrict__ pv = (const float4*)pred;
        float4* sv = (float4*)sh;
        const int base = bid * CTA_V4;
        #pragma unroll
        for (int i = 0; i < 6; i++) {            // 6*128 = 768 >= 672
            const int li = tid + i * THREADS_PER_CTA;
            if (li < CTA_V4 && base + li < TOTAL_V4)
                sv[li] = pv[base + li];
        }
    }

    const float area_b = fabsf(lw * lh);
    const float sqlx = sqrt_approx(lx);
    const float sqly = sqrt_approx(ly);

    __syncthreads();

    // ---- per-cell loss ----
    float local = 0.0f;
    const int cell = bid * CELLS_PER_CTA + tid;
    if (cell < N_CELLS) {
        const float* c = sh + tid * CELL_F;   // stride 21 words: conflict-free

        float v[CELL_F];
        #pragma unroll
        for (int i = 0; i < CELL_F; i++) v[i] = c[i];

        float inter[N_ANCHORS], den[N_ANCHORS];
        #pragma unroll
        for (int a = 0; a < N_ANCHORS; a++) {
            const float px = v[a * N_CH + 0];
            const float py = v[a * N_CH + 1];
            const float pw = v[a * N_CH + 2];
            const float ph = v[a * N_CH + 3];
            const float ax = fmaxf(px - pw * 0.5f, lx - lw * 0.5f);
            const float ay = fmaxf(py - ph * 0.5f, ly - lh * 0.5f);
            const float bx = fminf(px + pw * 0.5f, lx + lw * 0.5f);
            const float by = fminf(py + ph * 0.5f, ly + lh * 0.5f);
            const float in = fabsf(fmaxf(bx - ax, 0.0f) * fmaxf(by - ay, 0.0f));
            inter[a] = in;
            den[a] = fabsf(pw * ph) + area_b - in;   // union area > 0
        }

        // Division-free argmax, strict > keeps first max (jnp.argmax).
        int best = 0;
        if (inter[1] * den[0] > inter[0] * den[1]) best = 1;
        if (inter[2] * den[best] > inter[best] * den[2]) best = 2;

        const float b0 = v[best * N_CH + 0];
        const float b1 = v[best * N_CH + 1];
        const float b4 = v[best * N_CH + 4];
        const float b5 = v[best * N_CH + 5];
        const float b6 = v[best * N_CH + 6];

        const float dx = lx - b0;
        const float dy = ly - b1;
        const float xy_loss = dx * dx + dy * dy;

        // Reference uses label[0]/label[1], best[:,0]/best[:,1] in the sqrt
        // terms — replicated verbatim.
        const float swx = sqlx - sqrt_approx(b0);
        const float swy = sqly - sqrt_approx(b1);
        const float wh_loss = swx * swx + swy * swy;

        const bool has_obj = b4 > CONF_THRESH;
        float class_loss = 0.0f;
        if (has_obj) {
            const float d5 = l5 - b5;
            const float d6 = l6 - b6;
            class_loss = d5 * d5 + d6 * d6;
        }
        const float dc = lc - b4;
        const float conf_sq = dc * dc;
        const float conf_loss = has_obj ? conf_sq : NO_OBJECT * conf_sq;

        local = xy_loss + wh_loss + class_loss + conf_loss;
    }

    // ---- intra-warp reduce (fixed order -> deterministic) ----
    #pragma unroll
    for (int off = 16; off > 0; off >>= 1)
        local += __shfl_down_sync(0xFFFFFFFFu, local, off);

    if (lane == 0) warp_sums[wid] = local;
    __syncthreads();

    // ---- warp 0 combines the 4 warp sums, then one packed atomic ----
    if (wid == 0) {
        float s = (lane < 4) ? warp_sums[lane] : 0.0f;
        s += __shfl_down_sync(0xFFFFFFFFu, s, 2);
        s += __shfl_down_sync(0xFFFFFFFFu, s, 1);

        if (lane == 0) {
            // s >= 0 always (sum of squares / scaled squares).
            const unsigned long long fixed =
                (unsigned long long)__double2ll_rn((double)s * 0x1p40);
            const unsigned long long packed = fixed + COUNT_ONE;
            const unsigned long long old = atomicAdd(&g_accum, packed);
            const unsigned long long now = old + packed;
            if ((now >> 56) == (unsigned long long)N_CTAS) {
                // Last CTA: full sum already in-register. Store & reset.
                const double total =
                    (double)(long long)(now & SUM_MASK) * 0x1p-40;
                out[0] = (float)total;
                atomicExch(&g_accum, 0ULL);   // ready for next graph replay
            }
        }
    }
}

extern "C" void kernel_launch(void* const* d_in, const int* in_sizes, int n_in,
                              void* d_out, int out_size) {
    const float* pred  = (const float*)d_in[0];
    const float* label = (const float*)d_in[1];
    float* out = (float*)d_out;
    yolo_loss_kernel<<<N_CTAS, THREADS_PER_CTA>>>(pred, label, out);
}